// round 15
// baseline (speedup 1.0000x reference)
#include <cuda_runtime.h>
#include <cuda_fp16.h>
#include <cstdint>
#include <cstddef>

// ---------------------------------------------------------------------------
// Problem constants
// ---------------------------------------------------------------------------
static constexpr int NSTK  = 65536;
static constexpr int NFEAT = 768;
static constexpr int NH    = 512;
static constexpr int NACT  = 3;

// GEMM tiling: CTA 128(M) x 256(N) x 64(K), 256 threads, warp tile 64x64.
// B: 4-stage cp.async (32KB/stage, 128B rows). A: LDG->regs->convert->STS,
// double-buffered fp16 tile (2 x 16KB). 12 K-iterations (K=64 each).
static constexpr int NKIT = NFEAT / 64;          // 12
static constexpr int BSTAGE = 32768;             // 256 rows x 128B
static constexpr int BSTAGES = 4;
static constexpr int A16_OFF  = BSTAGES * BSTAGE;              // 131072
static constexpr int SMEM_DYN = A16_OFF + 2 * 16384;           // 163840

// ---------------------------------------------------------------------------
// Device scratch (static globals: allocation-free)
// ---------------------------------------------------------------------------
__device__ __half g_whh[NH * NFEAT];
__device__ float  g_hpart[512 * 512];              // [m_tile][col] colsum parts
__device__ float  g_dotp[(size_t)NSTK * 12];       // per-row 6 dots x 2 ntiles
__device__ float  g_cterm[NACT];

// ---------------------------------------------------------------------------
// PTX helpers (arch-agnostic, sm_80-level)
// ---------------------------------------------------------------------------
__device__ __forceinline__ uint32_t smem_u32(const void* p) {
    uint32_t a;
    asm("{ .reg .u64 t; cvta.to.shared.u64 t, %1; cvt.u32.u64 %0, t; }" : "=r"(a) : "l"(p));
    return a;
}
__device__ __forceinline__ void cpa16(uint32_t dst, const void* src) {
    asm volatile("cp.async.cg.shared.global [%0], [%1], 16;" :: "r"(dst), "l"(src));
}
__device__ __forceinline__ void cpa_commit() { asm volatile("cp.async.commit_group;"); }
template <int N> __device__ __forceinline__ void cpa_wait() {
    asm volatile("cp.async.wait_group %0;" :: "n"(N));
}
#define LDMX4(r, addr)                                                          \
    asm volatile("ldmatrix.sync.aligned.m8n8.x4.shared.b16 {%0,%1,%2,%3}, [%4];" \
        : "=r"((r)[0]), "=r"((r)[1]), "=r"((r)[2]), "=r"((r)[3]) : "r"(addr))

__device__ __forceinline__ void mma16816(float* d, const uint32_t* a, const uint32_t* b) {
    asm volatile(
        "mma.sync.aligned.m16n8k16.row.col.f32.f16.f16.f32 "
        "{%0,%1,%2,%3}, {%4,%5,%6,%7}, {%8,%9}, {%0,%1,%2,%3};"
        : "+f"(d[0]), "+f"(d[1]), "+f"(d[2]), "+f"(d[3])
        : "r"(a[0]), "r"(a[1]), "r"(a[2]), "r"(a[3]), "r"(b[0]), "r"(b[1]));
}
// 128B-row swizzle: granule (16B) index XORed with row&7 -> conflict-free
// ldmatrix (8 rows hit 8 distinct granules) and conflict-free STS.
__device__ __forceinline__ uint32_t soff128(int row, int g) {
    return (uint32_t)(row * 128 + ((g ^ (row & 7)) << 4));
}

// ---------------------------------------------------------------------------
// Kernel 0: W -> fp16 (tiny)
// ---------------------------------------------------------------------------
__global__ void k_wsplit(const float* __restrict__ wh) {
    int i = blockIdx.x * blockDim.x + threadIdx.x;   // 98304 float4 tasks
    float4 v = ((const float4*)wh)[i];
    ((__half2*)g_whh)[2 * i]     = __halves2half2(__float2half_rn(v.x), __float2half_rn(v.y));
    ((__half2*)g_whh)[2 * i + 1] = __halves2half2(__float2half_rn(v.z), __float2half_rn(v.w));
}

// ---------------------------------------------------------------------------
// Kernel 1: fused GEMM1 + epilogue. 256 threads, 8 warps (2m x 4n), warp 64x64.
//   h = relu(x @ Wh^T + bh) (fp16 in, fp32 accum; h never stored)
//   emits: per-CTA column sums -> g_hpart, per-row layer2 dots -> g_dotp
// grid (2, 512): blockIdx.x = ntile (256 N-cols), blockIdx.y = mtile (128 rows)
// ---------------------------------------------------------------------------
__global__ void __launch_bounds__(256, 1) k_gemm(const float* __restrict__ x,
                                                 const float* __restrict__ bh,
                                                 const float* __restrict__ Wf) {
    extern __shared__ char smem[];
    __shared__ float sbh[256];
    __shared__ float sWf1[3][256];
    __shared__ float sWf2[3][256];
    __shared__ float sred[8][64];
    __shared__ float sdot[4][128][6];
    const uint32_t sb = smem_u32(smem);

    const int tid = threadIdx.x, wid = tid >> 5, lid = tid & 31;
    const int ntile = blockIdx.x, mtile = blockIdx.y;

    sbh[tid] = bh[ntile * 256 + tid];
#pragma unroll
    for (int a = 0; a < 3; ++a) {
        sWf1[a][tid] = Wf[a * 1024 + ntile * 256 + tid];
        sWf2[a][tid] = Wf[a * 1024 + 512 + ntile * 256 + tid];
    }

    const char* pBh = (const char*)g_whh + (size_t)ntile * 256 * 1536;

    auto load_B = [&](int it, int s) {
        const uint32_t st = sb + s * BSTAGE;
#pragma unroll
        for (int i = 0; i < 8; ++i) {
            int idx = tid + i * 256;           // 2048 granules: 256 rows x 8
            int r = idx >> 3, g = idx & 7;
            cpa16(st + soff128(r, g),
                  pBh + (size_t)r * 1536 + (size_t)it * 128 + g * 16);
        }
        cpa_commit();
    };

    load_B(0, 0);
    load_B(1, 1);
    load_B(2, 2);

    // A fetch mapping: thread t covers row = t>>1 (of 128), half = t&1
    // (32 f32 = 128B of the 256B fp32 K-chunk row) -> 4 fp16 granules.
    const int arow = tid >> 1, ahalf = tid & 1;
    const char* pXme = (const char*)x + (size_t)(mtile * 128 + arow) * 3072 + ahalf * 128;
    uint32_t sts_addr[4];
#pragma unroll
    for (int q = 0; q < 4; ++q) sts_addr[q] = soff128(arow, ahalf * 4 + q);

    float4 pf[8];
    {
        const float4* s0 = (const float4*)(pXme);
#pragma unroll
        for (int q = 0; q < 8; ++q) pf[q] = s0[q];
    }

    float acc[4][8][4];
#pragma unroll
    for (int mi = 0; mi < 4; ++mi)
#pragma unroll
        for (int ni = 0; ni < 8; ++ni)
#pragma unroll
            for (int e = 0; e < 4; ++e) acc[mi][ni][e] = 0.0f;

    const int wm = (wid & 1) * 64;        // warp M offset (0, 64)
    const int wn = (wid >> 1) * 64;       // warp N offset (0, 64, 128, 192)
    const int c0 = lid >> 4;
    // fragment ldmatrix address components (XOR swizzle decomposed per thread)
    const int rA = wm + (lid & 15), r7a = rA & 7;
    const int rB = wn + (lid & 15), r7b = rB & 7;
    const uint32_t aBase = (uint32_t)(rA * 128 + ((c0 ^ (r7a & 1)) << 4));
    const uint32_t bBase = (uint32_t)(rB * 128 + ((c0 ^ (r7b & 1)) << 4));
    uint32_t joffA[4], joffB[4];
#pragma unroll
    for (int j = 0; j < 4; ++j) {
        joffA[j] = (uint32_t)(((2 * j) ^ (r7a & 6)) << 4);
        joffB[j] = (uint32_t)(((2 * j) ^ (r7b & 6)) << 4);
    }

    for (int it = 0; it < NKIT; ++it) {
        // convert prefetched A regs -> fp16, STS to double buffer (4 x uint4)
        const uint32_t aoffbuf = A16_OFF + (it & 1) * 16384;
#pragma unroll
        for (int q = 0; q < 4; ++q) {
            union { __half2 h[4]; uint4 u; } t0;
            t0.h[0] = __halves2half2(__float2half_rn(pf[2 * q].x), __float2half_rn(pf[2 * q].y));
            t0.h[1] = __halves2half2(__float2half_rn(pf[2 * q].z), __float2half_rn(pf[2 * q].w));
            t0.h[2] = __halves2half2(__float2half_rn(pf[2 * q + 1].x), __float2half_rn(pf[2 * q + 1].y));
            t0.h[3] = __halves2half2(__float2half_rn(pf[2 * q + 1].z), __float2half_rn(pf[2 * q + 1].w));
            *(uint4*)(smem + aoffbuf + sts_addr[q]) = t0.u;
        }
        // prefetch next A chunk (clamped; latency hidden under MMA phase)
        {
            const int kn = (it + 1 < NKIT) ? it + 1 : it;
            const float4* s0 = (const float4*)(pXme + (size_t)kn * 256);
#pragma unroll
            for (int q = 0; q < 8; ++q) pf[q] = s0[q];
        }

        cpa_wait<2>();
        __syncthreads();
        if (it + 3 < NKIT) load_B(it + 3, (it + 3) & 3);
        else cpa_commit();

        const uint32_t abuf = sb + aoffbuf;
        const uint32_t st = sb + (it & 3) * BSTAGE;

        // ---- MMA: 4 K16-halves; 8 ldmatrix.x4 then 32 MMAs per half ----
#pragma unroll
        for (int j = 0; j < 4; ++j) {
            uint32_t ah[4][4];
#pragma unroll
            for (int mi = 0; mi < 4; ++mi)
                LDMX4(ah[mi], abuf + aBase + mi * 2048 + joffA[j]);
            uint32_t bfr[8][2];
#pragma unroll
            for (int nq = 0; nq < 4; ++nq) {
                uint32_t t[4];
                LDMX4(t, st + bBase + nq * 2048 + joffB[j]);
                bfr[2 * nq][0] = t[0]; bfr[2 * nq][1] = t[2];
                bfr[2 * nq + 1][0] = t[1]; bfr[2 * nq + 1][1] = t[3];
            }
#pragma unroll
            for (int mi = 0; mi < 4; ++mi)
#pragma unroll
                for (int ni = 0; ni < 8; ++ni)
                    mma16816(acc[mi][ni], ah[mi], bfr[ni]);
        }
    }
    __syncthreads();

    // ---- Epilogue: bias + relu (in regs), colsums, layer-2 dot partials ----
    const int q2 = (lid & 3) * 2;
#pragma unroll
    for (int mi = 0; mi < 4; ++mi)
#pragma unroll
        for (int ni = 0; ni < 8; ++ni) {
            const int cl = wn + ni * 8 + q2;
            const float b0 = sbh[cl], b1 = sbh[cl + 1];
            acc[mi][ni][0] = fmaxf(acc[mi][ni][0] + b0, 0.0f);
            acc[mi][ni][1] = fmaxf(acc[mi][ni][1] + b1, 0.0f);
            acc[mi][ni][2] = fmaxf(acc[mi][ni][2] + b0, 0.0f);
            acc[mi][ni][3] = fmaxf(acc[mi][ni][3] + b1, 0.0f);
        }

    // column sums over this warp's 64 rows (fixed order)
#pragma unroll
    for (int ni = 0; ni < 8; ++ni) {
        float p0 = 0.0f, p1 = 0.0f;
#pragma unroll
        for (int mi = 0; mi < 4; ++mi) {
            p0 += acc[mi][ni][0] + acc[mi][ni][2];
            p1 += acc[mi][ni][1] + acc[mi][ni][3];
        }
#pragma unroll
        for (int off = 4; off < 32; off <<= 1) {
            p0 += __shfl_xor_sync(0xffffffffu, p0, off);
            p1 += __shfl_xor_sync(0xffffffffu, p1, off);
        }
        if (lid < 4) {
            sred[wid][ni * 8 + 2 * lid]     = p0;
            sred[wid][ni * 8 + 2 * lid + 1] = p1;
        }
    }

    // per-row dot partials with Wf1/Wf2 (6 values per row), per mi block
    const int wng = wid >> 1;
#pragma unroll
    for (int mi = 0; mi < 4; ++mi) {
        float dA[6] = {0, 0, 0, 0, 0, 0}, dB[6] = {0, 0, 0, 0, 0, 0};
#pragma unroll
        for (int ni = 0; ni < 8; ++ni) {
            const int cl = wn + ni * 8 + q2;
            const float v0 = acc[mi][ni][0], v1 = acc[mi][ni][1];
            const float v2 = acc[mi][ni][2], v3 = acc[mi][ni][3];
#pragma unroll
            for (int a = 0; a < 3; ++a) {
                const float w10 = sWf1[a][cl], w11 = sWf1[a][cl + 1];
                const float w20 = sWf2[a][cl], w21 = sWf2[a][cl + 1];
                dA[2 * a]     += v0 * w10 + v1 * w11;
                dA[2 * a + 1] += v0 * w20 + v1 * w21;
                dB[2 * a]     += v2 * w10 + v3 * w11;
                dB[2 * a + 1] += v2 * w20 + v3 * w21;
            }
        }
#pragma unroll
        for (int off = 1; off < 4; off <<= 1)
#pragma unroll
            for (int e = 0; e < 6; ++e) {
                dA[e] += __shfl_xor_sync(0xffffffffu, dA[e], off);
                dB[e] += __shfl_xor_sync(0xffffffffu, dB[e], off);
            }
        if ((lid & 3) == 0) {
            const int rA2 = wm + mi * 16 + (lid >> 2);
#pragma unroll
            for (int e = 0; e < 6; ++e) {
                sdot[wng][rA2][e]     = dA[e];
                sdot[wng][rA2 + 8][e] = dB[e];
            }
        }
    }
    __syncthreads();

    // finalize colsums (256 cols) and row dots (128 rows), fixed order
    {
        const int c = tid;                 // 0..255
        const int g = c >> 6;
        float cs = sred[2 * g][c & 63] + sred[2 * g + 1][c & 63];
        g_hpart[mtile * 512 + ntile * 256 + c] = cs;
    }
    if (tid < 128) {
        const int r = tid;
        float* dst = g_dotp + ((size_t)(mtile * 128 + r)) * 12 + ntile * 6;
#pragma unroll
        for (int e = 0; e < 6; ++e)
            dst[e] = sdot[0][r][e] + sdot[1][r][e] + sdot[2][r][e] + sdot[3][r][e];
    }
}

// ---------------------------------------------------------------------------
// Kernel 2: S colsum (fixed order) + cterm. <<<1, 512>>>
// ---------------------------------------------------------------------------
__global__ void k_pre(const float* __restrict__ Wf, const float* __restrict__ bf) {
    __shared__ float sS[512];
    const int g = threadIdx.x;
    float s = 0.0f;
    for (int m = 0; m < 512; ++m) s += g_hpart[m * 512 + g];
    sS[g] = s;
    __syncthreads();
    const float inv = 1.0f / (float)(NSTK - 1);
    if (g < 32) {
#pragma unroll
        for (int a = 0; a < NACT; ++a) {
            float p = 0.0f;
            for (int q = g; q < NH; q += 32) p += sS[q] * Wf[a * 1024 + 512 + q];
#pragma unroll
            for (int off = 16; off > 0; off >>= 1)
                p += __shfl_xor_sync(0xffffffffu, p, off);
            if (g == 0) g_cterm[a] = p * inv + bf[a];
        }
    }
}

// ---------------------------------------------------------------------------
// Kernel 3: combine dot partials -> out. 1 thread per stock.
// ---------------------------------------------------------------------------
__global__ void __launch_bounds__(256) k_out2(float* __restrict__ out) {
    __shared__ float sc[3];
    if (threadIdx.x < 3) sc[threadIdx.x] = g_cterm[threadIdx.x];
    __syncthreads();
    const int i = blockIdx.x * 256 + threadIdx.x;
    const float4 d0 = *(const float4*)(g_dotp + (size_t)i * 12);
    const float4 d1 = *(const float4*)(g_dotp + (size_t)i * 12 + 4);
    const float4 d2 = *(const float4*)(g_dotp + (size_t)i * 12 + 8);
    const float inv = 1.0f / (float)(NSTK - 1);
    // slots: [nt0: a0w1,a0w2,a1w1,a1w2,a2w1,a2w2][nt1: same]
    const float p0 = d0.x + d1.z, q0 = d0.y + d1.w;   // a0: w1, w2
    const float p1 = d0.z + d2.x, q1 = d0.w + d2.y;   // a1
    const float p2 = d1.x + d2.z, q2 = d1.y + d2.w;   // a2
    out[(size_t)i * 3 + 0] = fmaxf(p0 - q0 * inv + sc[0], 0.0f);
    out[(size_t)i * 3 + 1] = fmaxf(p1 - q1 * inv + sc[1], 0.0f);
    out[(size_t)i * 3 + 2] = fmaxf(p2 - q2 * inv + sc[2], 0.0f);
}

// ---------------------------------------------------------------------------
// Host launcher
// ---------------------------------------------------------------------------
extern "C" void kernel_launch(void* const* d_in, const int* in_sizes, int n_in,
                              void* d_out, int out_size) {
    const float *x = nullptr, *Wh = nullptr, *bh = nullptr, *Wf = nullptr, *bf = nullptr;
    for (int i = 0; i < n_in; ++i) {
        switch (in_sizes[i]) {
            case NSTK * NFEAT:  x  = (const float*)d_in[i]; break;  // 50331648
            case NH * NFEAT:    Wh = (const float*)d_in[i]; break;  // 393216
            case NH:            bh = (const float*)d_in[i]; break;  // 512
            case NACT * 2 * NH: Wf = (const float*)d_in[i]; break;  // 3072
            case NACT:          bf = (const float*)d_in[i]; break;  // 3
            default: break;
        }
    }
    float* out = (float*)d_out;

    static bool attr_set = false;
    if (!attr_set) {
        cudaFuncSetAttribute(k_gemm, cudaFuncAttributeMaxDynamicSharedMemorySize, SMEM_DYN);
        attr_set = true;
    }

    k_wsplit<<<384, 256>>>(Wh);
    k_gemm<<<dim3(2, 512), 256, SMEM_DYN>>>(x, bh, Wf);
    k_pre<<<1, 512>>>(Wf, bf);
    k_out2<<<NSTK / 256, 256>>>(out);
}

// round 16
// speedup vs baseline: 1.0478x; 1.0478x over previous
#include <cuda_runtime.h>
#include <cuda_fp16.h>
#include <cstdint>
#include <cstddef>

// ---------------------------------------------------------------------------
// Problem constants
// ---------------------------------------------------------------------------
static constexpr int NSTK  = 65536;
static constexpr int NFEAT = 768;
static constexpr int NH    = 512;
static constexpr int NACT  = 3;

// GEMM tiling: CTA 128(M) x 256(N) x 32(K), 256 threads, warp tile 64x64.
// B: 4-stage cp.async (16KB/stage). A: LDG->regs->convert->STS, double-buffered
// fp16 tile (2 x 8KB).
static constexpr int NKCH = NFEAT / 32;          // 24 K-chunks
static constexpr int STAGE_BYTES = 16384;        // B only: 256x32 f16
static constexpr int STAGES = 4;
static constexpr int A16_OFF  = STAGES * STAGE_BYTES;          // 65536
static constexpr int SMEM_DYN = A16_OFF + 2 * 8192;            // 81920

// ---------------------------------------------------------------------------
// Device scratch (static globals: allocation-free)
// ---------------------------------------------------------------------------
__device__ __half g_whh[NH * NFEAT];
__device__ float  g_hpart[512 * 512];              // [m_tile][col] colsum parts
__device__ float  g_S[512];                        // column sums of h
__device__ float  g_dotp[(size_t)NSTK * 12];       // per-row 6 dots x 2 ntiles
__device__ float  g_cterm[NACT];

// ---------------------------------------------------------------------------
// PTX helpers (arch-agnostic, sm_80-level)
// ---------------------------------------------------------------------------
__device__ __forceinline__ uint32_t smem_u32(const void* p) {
    uint32_t a;
    asm("{ .reg .u64 t; cvta.to.shared.u64 t, %1; cvt.u32.u64 %0, t; }" : "=r"(a) : "l"(p));
    return a;
}
__device__ __forceinline__ void cpa16(uint32_t dst, const void* src) {
    asm volatile("cp.async.cg.shared.global [%0], [%1], 16;" :: "r"(dst), "l"(src));
}
__device__ __forceinline__ void cpa_commit() { asm volatile("cp.async.commit_group;"); }
template <int N> __device__ __forceinline__ void cpa_wait() {
    asm volatile("cp.async.wait_group %0;" :: "n"(N));
}
#define LDMX4(r, addr)                                                          \
    asm volatile("ldmatrix.sync.aligned.m8n8.x4.shared.b16 {%0,%1,%2,%3}, [%4];" \
        : "=r"((r)[0]), "=r"((r)[1]), "=r"((r)[2]), "=r"((r)[3]) : "r"(addr))

__device__ __forceinline__ void mma16816(float* d, const uint32_t* a, const uint32_t* b) {
    asm volatile(
        "mma.sync.aligned.m16n8k16.row.col.f32.f16.f16.f32 "
        "{%0,%1,%2,%3}, {%4,%5,%6,%7}, {%8,%9}, {%0,%1,%2,%3};"
        : "+f"(d[0]), "+f"(d[1]), "+f"(d[2]), "+f"(d[3])
        : "r"(a[0]), "r"(a[1]), "r"(a[2]), "r"(a[3]), "r"(b[0]), "r"(b[1]));
}
// 64B-row swizzle for f16 tiles: granule ^= (row>>1)&3
__device__ __forceinline__ uint32_t soff(int row, int g) {
    return (uint32_t)(row * 64 + ((g ^ ((row >> 1) & 3)) << 4));
}

// ---------------------------------------------------------------------------
// Kernel 0: W -> fp16 (tiny)
// ---------------------------------------------------------------------------
__global__ void k_wsplit(const float* __restrict__ wh) {
    int i = blockIdx.x * blockDim.x + threadIdx.x;   // 98304 float4 tasks
    float4 v = ((const float4*)wh)[i];
    ((__half2*)g_whh)[2 * i]     = __halves2half2(__float2half_rn(v.x), __float2half_rn(v.y));
    ((__half2*)g_whh)[2 * i + 1] = __halves2half2(__float2half_rn(v.z), __float2half_rn(v.w));
}

// ---------------------------------------------------------------------------
// Kernel 1: fused GEMM1 + epilogue.
//   h = relu(x @ Wh^T + bh) (fp16 in, fp32 accum; h never stored)
//   emits: per-CTA column sums -> g_hpart, per-row layer2 dots -> g_dotp
// grid (2, 512): blockIdx.x = ntile (256 N-cols), blockIdx.y = mtile (128 rows)
// ---------------------------------------------------------------------------
__global__ void __launch_bounds__(256, 1) k_gemm(const float* __restrict__ x,
                                                 const float* __restrict__ bh,
                                                 const float* __restrict__ Wf) {
    extern __shared__ char smem[];
    __shared__ float sbh[256];
    __shared__ float sWf1[3][256];
    __shared__ float sWf2[3][256];
    __shared__ float sred[8][64];
    __shared__ float sdot[4][128][6];
    const uint32_t sb = smem_u32(smem);

    const int tid = threadIdx.x, wid = tid >> 5, lid = tid & 31;
    const int ntile = blockIdx.x, mtile = blockIdx.y;

    sbh[tid] = bh[ntile * 256 + tid];
#pragma unroll
    for (int a = 0; a < 3; ++a) {
        sWf1[a][tid] = Wf[a * 1024 + ntile * 256 + tid];
        sWf2[a][tid] = Wf[a * 1024 + 512 + ntile * 256 + tid];
    }

    const char* pBh = (const char*)g_whh + (size_t)ntile * 256 * 1536;

    auto load_B = [&](int k, int s) {
        const uint32_t st = sb + s * STAGE_BYTES;
#pragma unroll
        for (int it = 0; it < 4; ++it) {
            int idx = tid + it * 256;
            int r = idx >> 2, g = idx & 3;
            cpa16(st + soff(r, g),
                  pBh + (size_t)r * 1536 + (size_t)g * 16 + (size_t)k * 64);
        }
        cpa_commit();
    };

    load_B(0, 0);
    load_B(1, 1);
    load_B(2, 2);

    // A fetch mapping: thread t covers row = t>>1 (of 128), col-half = t&1
    // (16 f32 = 64B), i.e. granules {2*half, 2*half+1} of the 64B fp16 row.
    const int arow = tid >> 1, ahalf = tid & 1;
    const char* pXme = (const char*)x + (size_t)(mtile * 128 + arow) * 3072 + ahalf * 64;
    const uint32_t aw0 = soff(arow, 2 * ahalf);
    const uint32_t aw1 = soff(arow, 2 * ahalf + 1);

    float4 pf0, pf1, pf2, pf3;
    {
        const float4* s0 = (const float4*)(pXme);
        pf0 = s0[0]; pf1 = s0[1]; pf2 = s0[2]; pf3 = s0[3];
    }

    float acc[4][8][4];
#pragma unroll
    for (int mi = 0; mi < 4; ++mi)
#pragma unroll
        for (int ni = 0; ni < 8; ++ni)
#pragma unroll
            for (int e = 0; e < 4; ++e) acc[mi][ni][e] = 0.0f;

    const int wm = (wid & 1) * 64;        // warp M offset (0, 64)
    const int wn = (wid >> 1) * 64;       // warp N offset (0, 64, 128, 192)
    const int rloc = lid & 15, c0 = lid >> 4;
    const uint32_t aoff0 = soff(wm + rloc, c0);
    const uint32_t boff0 = soff(wn + rloc, c0);

    for (int k = 0; k < NKCH; ++k) {
        // convert prefetched A regs -> fp16, STS to double buffer
        const uint32_t abuf = sb + A16_OFF + (k & 1) * 8192;
        {
            union { __half2 h[4]; uint4 u; } t0, t1;
            t0.h[0] = __halves2half2(__float2half_rn(pf0.x), __float2half_rn(pf0.y));
            t0.h[1] = __halves2half2(__float2half_rn(pf0.z), __float2half_rn(pf0.w));
            t0.h[2] = __halves2half2(__float2half_rn(pf1.x), __float2half_rn(pf1.y));
            t0.h[3] = __halves2half2(__float2half_rn(pf1.z), __float2half_rn(pf1.w));
            t1.h[0] = __halves2half2(__float2half_rn(pf2.x), __float2half_rn(pf2.y));
            t1.h[1] = __halves2half2(__float2half_rn(pf2.z), __float2half_rn(pf2.w));
            t1.h[2] = __halves2half2(__float2half_rn(pf3.x), __float2half_rn(pf3.y));
            t1.h[3] = __halves2half2(__float2half_rn(pf3.z), __float2half_rn(pf3.w));
            *(uint4*)(smem + (abuf - sb) + aw0) = t0.u;
            *(uint4*)(smem + (abuf - sb) + aw1) = t1.u;
        }
        // prefetch next A chunk (clamped; latency hidden under MMA phase)
        {
            const int kn = (k + 1 < NKCH) ? k + 1 : k;
            const float4* s0 = (const float4*)(pXme + (size_t)kn * 128);
            pf0 = s0[0]; pf1 = s0[1]; pf2 = s0[2]; pf3 = s0[3];
        }

        cpa_wait<2>();
        __syncthreads();
        if (k + 3 < NKCH) load_B(k + 3, (k + 3) & 3);
        else cpa_commit();

        const uint32_t st = sb + (k & 3) * STAGE_BYTES;

        // ---- MMA phase with register double-buffered fragments ----
        // Load all j=0 frags + j=1 B frags up front; j=1 A frags issued after
        // the first mi-row of j=0 MMAs. Per-accumulator order stays j0 -> j1
        // (bit-identical to the reference schedule).
        uint32_t ah0[4][4], ah1[4][4], bf0[8][2], bf1[8][2];
#pragma unroll
        for (int mi = 0; mi < 4; ++mi)
            LDMX4(ah0[mi], abuf + (aoff0 + mi * 1024));
#pragma unroll
        for (int nq = 0; nq < 4; ++nq) {
            uint32_t t[4];
            LDMX4(t, st + (boff0 + nq * 1024));
            bf0[2 * nq][0] = t[0]; bf0[2 * nq][1] = t[2];
            bf0[2 * nq + 1][0] = t[1]; bf0[2 * nq + 1][1] = t[3];
        }
#pragma unroll
        for (int nq = 0; nq < 4; ++nq) {
            uint32_t t[4];
            LDMX4(t, st + ((boff0 + nq * 1024) ^ 32u));
            bf1[2 * nq][0] = t[0]; bf1[2 * nq][1] = t[2];
            bf1[2 * nq + 1][0] = t[1]; bf1[2 * nq + 1][1] = t[3];
        }
        // j=0, mi=0 burst
#pragma unroll
        for (int ni = 0; ni < 8; ++ni) mma16816(acc[0][ni], ah0[0], bf0[ni]);
        // j=1 A loads (latency overlapped by remaining j=0 MMAs)
#pragma unroll
        for (int mi = 0; mi < 4; ++mi)
            LDMX4(ah1[mi], abuf + ((aoff0 + mi * 1024) ^ 32u));
        // j=0, mi=1..3
#pragma unroll
        for (int mi = 1; mi < 4; ++mi)
#pragma unroll
            for (int ni = 0; ni < 8; ++ni) mma16816(acc[mi][ni], ah0[mi], bf0[ni]);
        // j=1 all
#pragma unroll
        for (int mi = 0; mi < 4; ++mi)
#pragma unroll
            for (int ni = 0; ni < 8; ++ni) mma16816(acc[mi][ni], ah1[mi], bf1[ni]);
    }
    __syncthreads();

    // ---- Epilogue: bias + relu (in regs), colsums, layer-2 dot partials ----
    const int q2 = (lid & 3) * 2;
#pragma unroll
    for (int mi = 0; mi < 4; ++mi)
#pragma unroll
        for (int ni = 0; ni < 8; ++ni) {
            const int cl = wn + ni * 8 + q2;
            const float b0 = sbh[cl], b1 = sbh[cl + 1];
            acc[mi][ni][0] = fmaxf(acc[mi][ni][0] + b0, 0.0f);
            acc[mi][ni][1] = fmaxf(acc[mi][ni][1] + b1, 0.0f);
            acc[mi][ni][2] = fmaxf(acc[mi][ni][2] + b0, 0.0f);
            acc[mi][ni][3] = fmaxf(acc[mi][ni][3] + b1, 0.0f);
        }

    // column sums over this warp's 64 rows (fixed order)
#pragma unroll
    for (int ni = 0; ni < 8; ++ni) {
        float p0 = 0.0f, p1 = 0.0f;
#pragma unroll
        for (int mi = 0; mi < 4; ++mi) {
            p0 += acc[mi][ni][0] + acc[mi][ni][2];
            p1 += acc[mi][ni][1] + acc[mi][ni][3];
        }
#pragma unroll
        for (int off = 4; off < 32; off <<= 1) {
            p0 += __shfl_xor_sync(0xffffffffu, p0, off);
            p1 += __shfl_xor_sync(0xffffffffu, p1, off);
        }
        if (lid < 4) {
            sred[wid][ni * 8 + 2 * lid]     = p0;
            sred[wid][ni * 8 + 2 * lid + 1] = p1;
        }
    }

    // per-row dot partials with Wf1/Wf2 (6 values per row), per mi block
    const int wng = wid >> 1;
#pragma unroll
    for (int mi = 0; mi < 4; ++mi) {
        float dA[6] = {0, 0, 0, 0, 0, 0}, dB[6] = {0, 0, 0, 0, 0, 0};
#pragma unroll
        for (int ni = 0; ni < 8; ++ni) {
            const int cl = wn + ni * 8 + q2;
            const float v0 = acc[mi][ni][0], v1 = acc[mi][ni][1];
            const float v2 = acc[mi][ni][2], v3 = acc[mi][ni][3];
#pragma unroll
            for (int a = 0; a < 3; ++a) {
                const float w10 = sWf1[a][cl], w11 = sWf1[a][cl + 1];
                const float w20 = sWf2[a][cl], w21 = sWf2[a][cl + 1];
                dA[2 * a]     += v0 * w10 + v1 * w11;
                dA[2 * a + 1] += v0 * w20 + v1 * w21;
                dB[2 * a]     += v2 * w10 + v3 * w11;
                dB[2 * a + 1] += v2 * w20 + v3 * w21;
            }
        }
#pragma unroll
        for (int off = 1; off < 4; off <<= 1)
#pragma unroll
            for (int e = 0; e < 6; ++e) {
                dA[e] += __shfl_xor_sync(0xffffffffu, dA[e], off);
                dB[e] += __shfl_xor_sync(0xffffffffu, dB[e], off);
            }
        if ((lid & 3) == 0) {
            const int rA = wm + mi * 16 + (lid >> 2);
#pragma unroll
            for (int e = 0; e < 6; ++e) {
                sdot[wng][rA][e]     = dA[e];
                sdot[wng][rA + 8][e] = dB[e];
            }
        }
    }
    __syncthreads();

    // finalize colsums (256 cols) and row dots (128 rows), fixed order
    {
        const int c = tid;                 // 0..255
        const int g = c >> 6;
        float cs = sred[2 * g][c & 63] + sred[2 * g + 1][c & 63];
        g_hpart[mtile * 512 + ntile * 256 + c] = cs;
    }
    if (tid < 128) {
        const int r = tid;
        float* dst = g_dotp + ((size_t)(mtile * 128 + r)) * 12 + ntile * 6;
#pragma unroll
        for (int e = 0; e < 6; ++e)
            dst[e] = sdot[0][r][e] + sdot[1][r][e] + sdot[2][r][e] + sdot[3][r][e];
    }
}

// ---------------------------------------------------------------------------
// Kernel 2a: column sums S over the 512 m-tiles. grid 2 x 256 threads,
// one column per thread, 8 interleaved accumulators (fixed order, MLP=8).
// ---------------------------------------------------------------------------
__global__ void __launch_bounds__(256) k_colsum() {
    const int c = blockIdx.x * 256 + threadIdx.x;    // 0..511
    float a0 = 0.f, a1 = 0.f, a2 = 0.f, a3 = 0.f;
    float a4 = 0.f, a5 = 0.f, a6 = 0.f, a7 = 0.f;
    for (int m = 0; m < 512; m += 8) {
        a0 += g_hpart[(m + 0) * 512 + c];
        a1 += g_hpart[(m + 1) * 512 + c];
        a2 += g_hpart[(m + 2) * 512 + c];
        a3 += g_hpart[(m + 3) * 512 + c];
        a4 += g_hpart[(m + 4) * 512 + c];
        a5 += g_hpart[(m + 5) * 512 + c];
        a6 += g_hpart[(m + 6) * 512 + c];
        a7 += g_hpart[(m + 7) * 512 + c];
    }
    g_S[c] = ((a0 + a1) + (a2 + a3)) + ((a4 + a5) + (a6 + a7));
}

// ---------------------------------------------------------------------------
// Kernel 2b: cterm[a] = (S . Wf2[a]) / (n-1) + bf[a]. <<<1, 32>>>
// ---------------------------------------------------------------------------
__global__ void k_cterm(const float* __restrict__ Wf, const float* __restrict__ bf) {
    const int g = threadIdx.x;
    const float inv = 1.0f / (float)(NSTK - 1);
#pragma unroll
    for (int a = 0; a < NACT; ++a) {
        float p = 0.0f;
        for (int q = g; q < NH; q += 32) p += g_S[q] * Wf[a * 1024 + 512 + q];
#pragma unroll
        for (int off = 16; off > 0; off >>= 1)
            p += __shfl_xor_sync(0xffffffffu, p, off);
        if (g == 0) g_cterm[a] = p * inv + bf[a];
    }
}

// ---------------------------------------------------------------------------
// Kernel 3: combine dot partials -> out. 1 thread per stock.
// ---------------------------------------------------------------------------
__global__ void __launch_bounds__(256) k_out2(float* __restrict__ out) {
    __shared__ float sc[3];
    if (threadIdx.x < 3) sc[threadIdx.x] = g_cterm[threadIdx.x];
    __syncthreads();
    const int i = blockIdx.x * 256 + threadIdx.x;
    const float4 d0 = *(const float4*)(g_dotp + (size_t)i * 12);
    const float4 d1 = *(const float4*)(g_dotp + (size_t)i * 12 + 4);
    const float4 d2 = *(const float4*)(g_dotp + (size_t)i * 12 + 8);
    const float inv = 1.0f / (float)(NSTK - 1);
    // slots: [nt0: a0w1,a0w2,a1w1,a1w2,a2w1,a2w2][nt1: same]
    const float p0 = d0.x + d1.z, q0 = d0.y + d1.w;   // a0: w1, w2
    const float p1 = d0.z + d2.x, q1 = d0.w + d2.y;   // a1
    const float p2 = d1.x + d2.z, q2 = d1.y + d2.w;   // a2
    out[(size_t)i * 3 + 0] = fmaxf(p0 - q0 * inv + sc[0], 0.0f);
    out[(size_t)i * 3 + 1] = fmaxf(p1 - q1 * inv + sc[1], 0.0f);
    out[(size_t)i * 3 + 2] = fmaxf(p2 - q2 * inv + sc[2], 0.0f);
}

// ---------------------------------------------------------------------------
// Host launcher
// ---------------------------------------------------------------------------
extern "C" void kernel_launch(void* const* d_in, const int* in_sizes, int n_in,
                              void* d_out, int out_size) {
    const float *x = nullptr, *Wh = nullptr, *bh = nullptr, *Wf = nullptr, *bf = nullptr;
    for (int i = 0; i < n_in; ++i) {
        switch (in_sizes[i]) {
            case NSTK * NFEAT:  x  = (const float*)d_in[i]; break;  // 50331648
            case NH * NFEAT:    Wh = (const float*)d_in[i]; break;  // 393216
            case NH:            bh = (const float*)d_in[i]; break;  // 512
            case NACT * 2 * NH: Wf = (const float*)d_in[i]; break;  // 3072
            case NACT:          bf = (const float*)d_in[i]; break;  // 3
            default: break;
        }
    }
    float* out = (float*)d_out;

    static bool attr_set = false;
    if (!attr_set) {
        cudaFuncSetAttribute(k_gemm, cudaFuncAttributeMaxDynamicSharedMemorySize, SMEM_DYN);
        attr_set = true;
    }

    k_wsplit<<<384, 256>>>(Wh);
    k_gemm<<<dim3(2, 512), 256, SMEM_DYN>>>(x, bh, Wf);
    k_colsum<<<2, 256>>>();
    k_cterm<<<1, 32>>>(Wf, bf);
    k_out2<<<NSTK / 256, 256>>>(out);
}